// round 1
// baseline (speedup 1.0000x reference)
#include <cuda_runtime.h>

#define BB 8
#define SS 1024
#define EE 1024
#define HH 16
#define DH 64

// Scratch for Q, K, V in [B,H,S,Dh] layout (32 MB each) — static device
// globals per the allocation rules.
__device__ __align__(128) float g_Q[(size_t)BB*HH*SS*DH];
__device__ __align__(128) float g_K[(size_t)BB*HH*SS*DH];
__device__ __align__(128) float g_V[(size_t)BB*HH*SS*DH];

// ---------------------------------------------------------------------------
// Kernel 1: fused QKV projection.
// grid = (M/128, H, 3), block = 256. Each block computes a 128x64 tile of
// one of Q/K/V for one head: [128 x 1024] x [1024 x 64].
// ---------------------------------------------------------------------------
__global__ __launch_bounds__(256) void qkv_kernel(
    const float* __restrict__ x,
    const float* __restrict__ Wq, const float* __restrict__ bq,
    const float* __restrict__ Wk, const float* __restrict__ bk,
    const float* __restrict__ Wv, const float* __restrict__ bv)
{
    __shared__ float Xs[32][132];   // k-major, transposed X tile (pad 4)
    __shared__ float Ws[32][64];    // [k][n]

    const int z = blockIdx.z;
    const float* W    = (z == 0) ? Wq : ((z == 1) ? Wk : Wv);
    const float* bias = (z == 0) ? bq : ((z == 1) ? bk : bv);
    float* outp       = (z == 0) ? g_Q : ((z == 1) ? g_K : g_V);

    const int h  = blockIdx.y;
    const int m0 = blockIdx.x * 128;
    W    += (size_t)h * EE * DH;
    bias += h * DH;
    const int b  = m0 / SS;
    const int s0 = m0 % SS;
    outp += ((size_t)(b * HH + h) * SS + s0) * DH;

    const int tid = threadIdx.x;
    const int tx  = tid & 15;
    const int ty  = tid >> 4;

    const int lr = tid >> 1;          // 0..127 : x row within tile
    const int lc = (tid & 1) * 16;    // k offset within 32-wide k-tile

    float acc[8][4];
    #pragma unroll
    for (int i = 0; i < 8; i++)
        #pragma unroll
        for (int j = 0; j < 4; j++) acc[i][j] = 0.f;

    for (int k0 = 0; k0 < EE; k0 += 32) {
        // Load X tile (transposed into smem)
        const float4* xv = (const float4*)(x + (size_t)(m0 + lr) * EE + k0 + lc);
        #pragma unroll
        for (int j = 0; j < 4; j++) {
            float4 v = xv[j];
            Xs[lc + 4*j + 0][lr] = v.x;
            Xs[lc + 4*j + 1][lr] = v.y;
            Xs[lc + 4*j + 2][lr] = v.z;
            Xs[lc + 4*j + 3][lr] = v.w;
        }
        // Load W tile (contiguous 32x64)
        const float4* wv  = (const float4*)(W + (size_t)k0 * DH);
        float4*       ws4 = (float4*)&Ws[0][0];
        ws4[tid]       = wv[tid];
        ws4[tid + 256] = wv[tid + 256];
        __syncthreads();

        #pragma unroll
        for (int kk = 0; kk < 32; kk++) {
            float4 a0 = *(const float4*)&Xs[kk][ty * 8];
            float4 a1 = *(const float4*)&Xs[kk][ty * 8 + 4];
            float4 bbv = *(const float4*)&Ws[kk][tx * 4];
            float a[8] = {a0.x, a0.y, a0.z, a0.w, a1.x, a1.y, a1.z, a1.w};
            float bj[4] = {bbv.x, bbv.y, bbv.z, bbv.w};
            #pragma unroll
            for (int i = 0; i < 8; i++)
                #pragma unroll
                for (int j = 0; j < 4; j++)
                    acc[i][j] = fmaf(a[i], bj[j], acc[i][j]);
        }
        __syncthreads();
    }

    float4 b4 = *(const float4*)&bias[tx * 4];
    #pragma unroll
    for (int i = 0; i < 8; i++) {
        int r = ty * 8 + i;
        float4 v = { acc[i][0] + b4.x, acc[i][1] + b4.y,
                     acc[i][2] + b4.z, acc[i][3] + b4.w };
        *(float4*)&outp[(size_t)r * DH + tx * 4] = v;
    }
}

// ---------------------------------------------------------------------------
// Kernel 2: flash attention + residual epilogue.
// grid = (S/128, B*H), block = 256. Each block: 128 query rows of one (b,h),
// streams K/V in 64-key tiles with online softmax; writes
// out = x + attn_out directly (no separate residual kernel).
// ---------------------------------------------------------------------------
__global__ __launch_bounds__(256) void attn_kernel(
    const float* __restrict__ x, float* __restrict__ out)
{
    extern __shared__ float sm[];
    float* Qs = sm;                 // [64][132]  d-major (scaled Q^T)
    float* Ks = Qs + 64 * 132;      // [64][68]   d-major (K^T)
    float* Vs = Ks + 64 * 68;       // [64][64]   t-major
    float* Ps = Vs + 64 * 64;       // [128][65]  row-major P

    const int tid = threadIdx.x;
    const int tx  = tid & 15;
    const int ty  = tid >> 4;
    const int bh  = blockIdx.y;
    const int b   = bh >> 4;
    const int h   = bh & 15;
    const int q0  = blockIdx.x * 128;

    const float* Qg = g_Q + ((size_t)bh * SS + q0) * DH;
    const float* Kg = g_K + (size_t)bh * SS * DH;
    const float* Vg = g_V + (size_t)bh * SS * DH;

    // Load Q tile transposed, folding in the 1/sqrt(E) = 1/32 scale.
    {
        const int r  = tid >> 1;
        const int cb = (tid & 1) * 32;
        const float4* qv = (const float4*)(Qg + (size_t)r * DH + cb);
        const float sc = 0.03125f;
        #pragma unroll
        for (int j = 0; j < 8; j++) {
            float4 v = qv[j];
            int d = cb + 4 * j;
            Qs[(d + 0) * 132 + r] = v.x * sc;
            Qs[(d + 1) * 132 + r] = v.y * sc;
            Qs[(d + 2) * 132 + r] = v.z * sc;
            Qs[(d + 3) * 132 + r] = v.w * sc;
        }
    }

    float o[8][4];
    float mi[8], li[8];
    #pragma unroll
    for (int i = 0; i < 8; i++) {
        mi[i] = -1e30f;
        li[i] = 0.f;
        #pragma unroll
        for (int j = 0; j < 4; j++) o[i][j] = 0.f;
    }

    for (int t0 = 0; t0 < SS; t0 += 64) {
        __syncthreads();   // previous iteration's PV reads done before reload
        // Load K tile transposed (d-major)
        {
            const int t  = tid >> 2;
            const int cb = (tid & 3) * 16;
            const float4* kv = (const float4*)(Kg + (size_t)(t0 + t) * DH + cb);
            #pragma unroll
            for (int j = 0; j < 4; j++) {
                float4 v = kv[j];
                int d = cb + 4 * j;
                Ks[(d + 0) * 68 + t] = v.x;
                Ks[(d + 1) * 68 + t] = v.y;
                Ks[(d + 2) * 68 + t] = v.z;
                Ks[(d + 3) * 68 + t] = v.w;
            }
            // V tile straight copy
            const float4* vv  = (const float4*)(Vg + (size_t)t0 * DH);
            float4*       vs4 = (float4*)Vs;
            #pragma unroll
            for (int j = 0; j < 4; j++) vs4[tid + j * 256] = vv[tid + j * 256];
        }
        __syncthreads();

        // scores S = Qs^T . Ks  (inner dim d = 64)
        float s_[8][4];
        #pragma unroll
        for (int i = 0; i < 8; i++)
            #pragma unroll
            for (int j = 0; j < 4; j++) s_[i][j] = 0.f;

        #pragma unroll 8
        for (int d = 0; d < 64; d++) {
            float4 a0 = *(const float4*)&Qs[d * 132 + ty * 8];
            float4 a1 = *(const float4*)&Qs[d * 132 + ty * 8 + 4];
            float4 kb = *(const float4*)&Ks[d * 68 + tx * 4];
            float a[8]  = {a0.x, a0.y, a0.z, a0.w, a1.x, a1.y, a1.z, a1.w};
            float kk[4] = {kb.x, kb.y, kb.z, kb.w};
            #pragma unroll
            for (int i = 0; i < 8; i++)
                #pragma unroll
                for (int j = 0; j < 4; j++)
                    s_[i][j] = fmaf(a[i], kk[j], s_[i][j]);
        }

        // online softmax (row stats reduced across the 16 tx lanes, which are
        // contiguous within a half-warp: tid = ty*16+tx)
        #pragma unroll
        for (int i = 0; i < 8; i++) {
            float mx = fmaxf(fmaxf(s_[i][0], s_[i][1]), fmaxf(s_[i][2], s_[i][3]));
            mx = fmaxf(mx, __shfl_xor_sync(0xffffffffu, mx, 1));
            mx = fmaxf(mx, __shfl_xor_sync(0xffffffffu, mx, 2));
            mx = fmaxf(mx, __shfl_xor_sync(0xffffffffu, mx, 4));
            mx = fmaxf(mx, __shfl_xor_sync(0xffffffffu, mx, 8));
            float mnew = fmaxf(mi[i], mx);
            float corr = __expf(mi[i] - mnew);
            mi[i] = mnew;
            float rs = 0.f;
            #pragma unroll
            for (int j = 0; j < 4; j++) {
                s_[i][j] = __expf(s_[i][j] - mnew);
                rs += s_[i][j];
            }
            rs += __shfl_xor_sync(0xffffffffu, rs, 1);
            rs += __shfl_xor_sync(0xffffffffu, rs, 2);
            rs += __shfl_xor_sync(0xffffffffu, rs, 4);
            rs += __shfl_xor_sync(0xffffffffu, rs, 8);
            li[i] = li[i] * corr + rs;
            #pragma unroll
            for (int j = 0; j < 4; j++) o[i][j] *= corr;
            // stash P (row-major, pad 65 keeps the column reads conflict-free)
            #pragma unroll
            for (int j = 0; j < 4; j++)
                Ps[(ty * 8 + i) * 65 + tx * 4 + j] = s_[i][j];
        }
        __syncthreads();

        // O += P . V  (inner dim t = 64)
        #pragma unroll 8
        for (int t = 0; t < 64; t++) {
            float4 vv = *(const float4*)&Vs[t * 64 + tx * 4];
            #pragma unroll
            for (int i = 0; i < 8; i++) {
                float p = Ps[(ty * 8 + i) * 65 + t];
                o[i][0] = fmaf(p, vv.x, o[i][0]);
                o[i][1] = fmaf(p, vv.y, o[i][1]);
                o[i][2] = fmaf(p, vv.z, o[i][2]);
                o[i][3] = fmaf(p, vv.w, o[i][3]);
            }
        }
    }

    // Epilogue: normalize, add residual x, scatter heads into [B,S,E]
    #pragma unroll
    for (int i = 0; i < 8; i++) {
        float inv = 1.f / li[i];
        int srow = q0 + ty * 8 + i;
        size_t idx = ((size_t)(b * SS + srow)) * EE + h * DH + tx * 4;
        float4 xv = *(const float4*)&x[idx];
        float4 r = { xv.x + o[i][0] * inv, xv.y + o[i][1] * inv,
                     xv.z + o[i][2] * inv, xv.w + o[i][3] * inv };
        *(float4*)&out[idx] = r;
    }
}

// ---------------------------------------------------------------------------
extern "C" void kernel_launch(void* const* d_in, const int* in_sizes, int n_in,
                              void* d_out, int out_size)
{
    const float* x  = (const float*)d_in[0];
    const float* Wq = (const float*)d_in[1];
    const float* bq = (const float*)d_in[2];
    const float* Wk = (const float*)d_in[3];
    const float* bk = (const float*)d_in[4];
    const float* Wv = (const float*)d_in[5];
    const float* bv = (const float*)d_in[6];
    float* out = (float*)d_out;

    const int smem_bytes = (64 * 132 + 64 * 68 + 64 * 64 + 128 * 65) * 4; // 100864
    cudaFuncSetAttribute(attn_kernel,
                         cudaFuncAttributeMaxDynamicSharedMemorySize, smem_bytes);

    qkv_kernel<<<dim3(64, 16, 3), 256>>>(x, Wq, bq, Wk, bk, Wv, bv);
    attn_kernel<<<dim3(8, 128), 256, smem_bytes>>>(x, out);
}

// round 2
// speedup vs baseline: 2.9185x; 2.9185x over previous
#include <cuda_runtime.h>
#include <cstdint>

#define BB 8
#define SS 1024
#define EE 1024
#define HH 16
#define DH 64

__device__ __align__(128) float g_Q[(size_t)BB*HH*SS*DH];
__device__ __align__(128) float g_K[(size_t)BB*HH*SS*DH];
__device__ __align__(128) float g_V[(size_t)BB*HH*SS*DH];

__device__ __forceinline__ uint32_t f2tf(float x) {
    uint32_t r; asm("cvt.rna.tf32.f32 %0, %1;" : "=r"(r) : "f"(x)); return r;
}

__device__ __forceinline__ void mma8(float* c,
    uint32_t a0, uint32_t a1, uint32_t a2, uint32_t a3,
    uint32_t b0, uint32_t b1)
{
    asm volatile(
        "mma.sync.aligned.m16n8k8.row.col.f32.tf32.tf32.f32 "
        "{%0,%1,%2,%3}, {%4,%5,%6,%7}, {%8,%9}, {%0,%1,%2,%3};"
        : "+f"(c[0]), "+f"(c[1]), "+f"(c[2]), "+f"(c[3])
        : "r"(a0), "r"(a1), "r"(a2), "r"(a3), "r"(b0), "r"(b1));
}

// ---------------------------------------------------------------------------
// Kernel 1: fused QKV projection as one GEMM C[8192,3072] = X[8192,1024] * W.
// Block tile 128x128 (BK=32), warp tile 64x32 (warps 2m x 4n), tf32 mma.
// n-block covers 2 heads of one of {Q,K,V}.
// ---------------------------------------------------------------------------
__global__ __launch_bounds__(256, 2) void qkv_kernel(
    const float* __restrict__ x,
    const float* __restrict__ Wq, const float* __restrict__ bq,
    const float* __restrict__ Wk, const float* __restrict__ bk,
    const float* __restrict__ Wv, const float* __restrict__ bv)
{
    __shared__ uint32_t As[128 * 36];   // [m][k], pad 4 -> frag addr = 4g+tg
    __shared__ uint32_t Bs[32 * 132];   // [k][n], pad 4 -> frag addr = 4tg+g

    const int tid  = threadIdx.x;
    const int lane = tid & 31;
    const int wid  = tid >> 5;
    const int g    = lane >> 2;
    const int tg   = lane & 3;
    const int wm   = (wid >> 2) * 64;
    const int wn   = (wid & 3) * 32;

    const int nb = blockIdx.y;
    const int z  = nb >> 3;
    const int h0 = (nb & 7) * 2;
    const float* W    = (z == 0) ? Wq : ((z == 1) ? Wk : Wv);
    const float* bias = (z == 0) ? bq : ((z == 1) ? bk : bv);
    float* outp       = (z == 0) ? g_Q : ((z == 1) ? g_K : g_V);

    const int m0 = blockIdx.x * 128;

    int aM[4], aQ[4], bK[4], bC[4];
    #pragma unroll
    for (int r = 0; r < 4; r++) {
        int ia = tid + r * 256;
        aM[r] = ia >> 3;  aQ[r] = (ia & 7) * 4;
        bK[r] = ia >> 5;  bC[r] = (ia & 31) * 4;
    }

    float4 stA[4], stB[4];
    #pragma unroll
    for (int r = 0; r < 4; r++) {
        stA[r] = *(const float4*)(x + (size_t)(m0 + aM[r]) * EE + aQ[r]);
        int h = h0 + (bC[r] >> 6), d = bC[r] & 63;
        stB[r] = *(const float4*)(W + ((size_t)h * EE + bK[r]) * DH + d);
    }

    float c[4][4][4];
    #pragma unroll
    for (int i = 0; i < 4; i++)
        #pragma unroll
        for (int j = 0; j < 4; j++)
            #pragma unroll
            for (int k = 0; k < 4; k++) c[i][j][k] = 0.f;

    for (int kt = 0; kt < 32; kt++) {
        __syncthreads();
        #pragma unroll
        for (int r = 0; r < 4; r++) {
            uint4 ua = { f2tf(stA[r].x), f2tf(stA[r].y), f2tf(stA[r].z), f2tf(stA[r].w) };
            *(uint4*)&As[aM[r] * 36 + aQ[r]] = ua;
            uint4 ub = { f2tf(stB[r].x), f2tf(stB[r].y), f2tf(stB[r].z), f2tf(stB[r].w) };
            *(uint4*)&Bs[bK[r] * 132 + bC[r]] = ub;
        }
        __syncthreads();
        if (kt < 31) {
            int k0 = (kt + 1) * 32;
            #pragma unroll
            for (int r = 0; r < 4; r++) {
                stA[r] = *(const float4*)(x + (size_t)(m0 + aM[r]) * EE + k0 + aQ[r]);
                int h = h0 + (bC[r] >> 6), d = bC[r] & 63;
                stB[r] = *(const float4*)(W + ((size_t)h * EE + (k0 + bK[r])) * DH + d);
            }
        }
        #pragma unroll
        for (int ks = 0; ks < 4; ks++) {
            uint32_t a[4][4], bfr[4][2];
            #pragma unroll
            for (int mf = 0; mf < 4; mf++) {
                const uint32_t* p = &As[(wm + mf * 16 + g) * 36 + ks * 8 + tg];
                a[mf][0] = p[0];        a[mf][2] = p[4];
                a[mf][1] = p[8 * 36];   a[mf][3] = p[8 * 36 + 4];
            }
            #pragma unroll
            for (int nf = 0; nf < 4; nf++) {
                const uint32_t* p = &Bs[(ks * 8 + tg) * 132 + wn + nf * 8 + g];
                bfr[nf][0] = p[0];  bfr[nf][1] = p[4 * 132];
            }
            #pragma unroll
            for (int mf = 0; mf < 4; mf++)
                #pragma unroll
                for (int nf = 0; nf < 4; nf++)
                    mma8(c[mf][nf], a[mf][0], a[mf][1], a[mf][2], a[mf][3],
                         bfr[nf][0], bfr[nf][1]);
        }
    }

    // epilogue: add bias, scatter to g_{Q,K,V} in [B,H,S,Dh]
    const int b     = blockIdx.x >> 3;
    const int sbase = (m0 & 1023) + wm + g;
    #pragma unroll
    for (int nf = 0; nf < 4; nf++) {
        int col = wn + nf * 8 + 2 * tg;
        int h = h0 + (col >> 6), d = col & 63;
        float2 bv2 = *(const float2*)(bias + h * DH + d);
        float* ob = outp + (size_t)(b * HH + h) * SS * DH + d;
        #pragma unroll
        for (int mf = 0; mf < 4; mf++) {
            int s0 = sbase + mf * 16;
            float2 v0 = { c[mf][nf][0] + bv2.x, c[mf][nf][1] + bv2.y };
            float2 v1 = { c[mf][nf][2] + bv2.x, c[mf][nf][3] + bv2.y };
            *(float2*)(ob + (size_t)s0 * DH)       = v0;
            *(float2*)(ob + (size_t)(s0 + 8) * DH) = v1;
        }
    }
}

// ---------------------------------------------------------------------------
// Kernel 2: flash attention (tf32 mma) + fused residual epilogue.
// Block: 128 Q-rows of one (b,h); 64-key tiles; warps 4m x 2n (32x32 tiles).
// ---------------------------------------------------------------------------
__global__ __launch_bounds__(256, 2) void attn_kernel(
    const float* __restrict__ x, float* __restrict__ out)
{
    extern __shared__ uint32_t sm[];
    uint32_t* Qs = sm;                 // [128][68] tf32, pre-scaled by 1/32
    uint32_t* Ks = Qs + 128 * 68;      // [64][68]
    uint32_t* Vs = Ks + 64 * 68;       // [64][72]
    uint32_t* Ps = Vs + 64 * 72;       // [128][68]
    float* redm  = (float*)(Ps + 128 * 68);  // [128][2]
    float* reds  = redm + 256;               // [128][2]

    const int tid  = threadIdx.x;
    const int lane = tid & 31;
    const int wid  = tid >> 5;
    const int g    = lane >> 2;
    const int tg   = lane & 3;
    const int mg   = wid >> 1;   // m-group: 32 rows
    const int nh   = wid & 1;    // n-half:  32 cols

    const int bh = blockIdx.y;
    const int q0 = blockIdx.x * 128;
    const float* Qg = g_Q + ((size_t)bh * SS + q0) * DH;
    const float* Kg = g_K + (size_t)bh * SS * DH;
    const float* Vg = g_V + (size_t)bh * SS * DH;

    // Q tile: scale by 1/sqrt(E)=1/32, convert to tf32
    #pragma unroll
    for (int r = 0; r < 8; r++) {
        int idx = tid + r * 256;
        int m = idx >> 4, q = (idx & 15) * 4;
        float4 v = *(const float4*)(Qg + (size_t)m * DH + q);
        uint4 u = { f2tf(v.x * 0.03125f), f2tf(v.y * 0.03125f),
                    f2tf(v.z * 0.03125f), f2tf(v.w * 0.03125f) };
        *(uint4*)&Qs[m * 68 + q] = u;
    }

    float o[2][4][4];
    float mi[2][2], li[2][2];
    #pragma unroll
    for (int mf = 0; mf < 2; mf++) {
        mi[mf][0] = mi[mf][1] = -1e30f;
        li[mf][0] = li[mf][1] = 0.f;
        #pragma unroll
        for (int nf = 0; nf < 4; nf++)
            #pragma unroll
            for (int k = 0; k < 4; k++) o[mf][nf][k] = 0.f;
    }

    for (int t0 = 0; t0 < SS; t0 += 64) {
        __syncthreads();
        #pragma unroll
        for (int r = 0; r < 4; r++) {
            int idx = tid + r * 256;
            int t = idx >> 4, q = (idx & 15) * 4;
            float4 kv = *(const float4*)(Kg + (size_t)(t0 + t) * DH + q);
            uint4 uk = { f2tf(kv.x), f2tf(kv.y), f2tf(kv.z), f2tf(kv.w) };
            *(uint4*)&Ks[t * 68 + q] = uk;
            float4 vv = *(const float4*)(Vg + (size_t)(t0 + t) * DH + q);
            uint4 uv = { f2tf(vv.x), f2tf(vv.y), f2tf(vv.z), f2tf(vv.w) };
            *(uint4*)&Vs[t * 72 + q] = uv;
        }
        __syncthreads();

        // S = Q K^T  (k-dim = Dh = 64 -> 8 ksteps)
        float s[2][4][4];
        #pragma unroll
        for (int mf = 0; mf < 2; mf++)
            #pragma unroll
            for (int nf = 0; nf < 4; nf++)
                #pragma unroll
                for (int k = 0; k < 4; k++) s[mf][nf][k] = 0.f;

        #pragma unroll
        for (int ks = 0; ks < 8; ks++) {
            uint32_t a[2][4], bfr[4][2];
            #pragma unroll
            for (int mf = 0; mf < 2; mf++) {
                const uint32_t* p = &Qs[(mg * 32 + mf * 16 + g) * 68 + ks * 8 + tg];
                a[mf][0] = p[0];        a[mf][2] = p[4];
                a[mf][1] = p[8 * 68];   a[mf][3] = p[8 * 68 + 4];
            }
            #pragma unroll
            for (int nf = 0; nf < 4; nf++) {
                const uint32_t* p = &Ks[(nh * 32 + nf * 8 + g) * 68 + ks * 8 + tg];
                bfr[nf][0] = p[0];  bfr[nf][1] = p[4];
            }
            #pragma unroll
            for (int mf = 0; mf < 2; mf++)
                #pragma unroll
                for (int nf = 0; nf < 4; nf++)
                    mma8(s[mf][nf], a[mf][0], a[mf][1], a[mf][2], a[mf][3],
                         bfr[nf][0], bfr[nf][1]);
        }

        // softmax pass 1: per-(warp,row) max partials
        #pragma unroll
        for (int mf = 0; mf < 2; mf++)
            #pragma unroll
            for (int rh = 0; rh < 2; rh++) {
                float v = -1e30f;
                #pragma unroll
                for (int nf = 0; nf < 4; nf++)
                    v = fmaxf(v, fmaxf(s[mf][nf][rh * 2], s[mf][nf][rh * 2 + 1]));
                v = fmaxf(v, __shfl_xor_sync(0xffffffffu, v, 1));
                v = fmaxf(v, __shfl_xor_sync(0xffffffffu, v, 2));
                if (tg == 0)
                    redm[(mg * 32 + mf * 16 + rh * 8 + g) * 2 + nh] = v;
            }
        __syncthreads();

        // softmax pass 2: exp, partial sums, P -> smem(tf32)
        float corr[2][2];
        #pragma unroll
        for (int mf = 0; mf < 2; mf++)
            #pragma unroll
            for (int rh = 0; rh < 2; rh++) {
                int row = mg * 32 + mf * 16 + rh * 8 + g;
                float rmax = fmaxf(redm[row * 2], redm[row * 2 + 1]);
                float mnew = fmaxf(mi[mf][rh], rmax);
                corr[mf][rh] = __expf(mi[mf][rh] - mnew);
                mi[mf][rh] = mnew;
                float psum = 0.f;
                #pragma unroll
                for (int nf = 0; nf < 4; nf++) {
                    #pragma unroll
                    for (int cc = 0; cc < 2; cc++) {
                        float p = __expf(s[mf][nf][rh * 2 + cc] - mnew);
                        psum += p;
                        Ps[row * 68 + nh * 32 + nf * 8 + 2 * tg + cc] = f2tf(p);
                    }
                }
                psum += __shfl_xor_sync(0xffffffffu, psum, 1);
                psum += __shfl_xor_sync(0xffffffffu, psum, 2);
                if (tg == 0) reds[row * 2 + nh] = psum;
            }
        __syncthreads();

        #pragma unroll
        for (int mf = 0; mf < 2; mf++)
            #pragma unroll
            for (int rh = 0; rh < 2; rh++) {
                int row = mg * 32 + mf * 16 + rh * 8 + g;
                li[mf][rh] = li[mf][rh] * corr[mf][rh] + reds[row * 2] + reds[row * 2 + 1];
                #pragma unroll
                for (int nf = 0; nf < 4; nf++) {
                    o[mf][nf][rh * 2]     *= corr[mf][rh];
                    o[mf][nf][rh * 2 + 1] *= corr[mf][rh];
                }
            }

        // O += P V  (k-dim = 64 keys -> 8 ksteps)
        #pragma unroll
        for (int ks = 0; ks < 8; ks++) {
            uint32_t a[2][4], bfr[4][2];
            #pragma unroll
            for (int mf = 0; mf < 2; mf++) {
                const uint32_t* p = &Ps[(mg * 32 + mf * 16 + g) * 68 + ks * 8 + tg];
                a[mf][0] = p[0];        a[mf][2] = p[4];
                a[mf][1] = p[8 * 68];   a[mf][3] = p[8 * 68 + 4];
            }
            #pragma unroll
            for (int nf = 0; nf < 4; nf++) {
                const uint32_t* p = &Vs[(ks * 8 + tg) * 72 + nh * 32 + nf * 8 + g];
                bfr[nf][0] = p[0];  bfr[nf][1] = p[4 * 72];
            }
            #pragma unroll
            for (int mf = 0; mf < 2; mf++)
                #pragma unroll
                for (int nf = 0; nf < 4; nf++)
                    mma8(o[mf][nf], a[mf][0], a[mf][1], a[mf][2], a[mf][3],
                         bfr[nf][0], bfr[nf][1]);
        }
    }

    // epilogue: out = x + O/li, scatter head slice into [B,S,E]
    const int b = bh >> 4, h = bh & 15;
    #pragma unroll
    for (int mf = 0; mf < 2; mf++)
        #pragma unroll
        for (int rh = 0; rh < 2; rh++) {
            float inv = 1.f / li[mf][rh];
            int r = mg * 32 + mf * 16 + rh * 8 + g;
            size_t base = ((size_t)(b * SS + q0 + r)) * EE + h * DH;
            #pragma unroll
            for (int nf = 0; nf < 4; nf++) {
                int d = nh * 32 + nf * 8 + 2 * tg;
                float2 xv = *(const float2*)(x + base + d);
                float2 ov = { xv.x + o[mf][nf][rh * 2] * inv,
                              xv.y + o[mf][nf][rh * 2 + 1] * inv };
                *(float2*)(out + base + d) = ov;
            }
        }
}

// ---------------------------------------------------------------------------
extern "C" void kernel_launch(void* const* d_in, const int* in_sizes, int n_in,
                              void* d_out, int out_size)
{
    const float* x  = (const float*)d_in[0];
    const float* Wq = (const float*)d_in[1];
    const float* bq = (const float*)d_in[2];
    const float* Wk = (const float*)d_in[3];
    const float* bk = (const float*)d_in[4];
    const float* Wv = (const float*)d_in[5];
    const float* bv = (const float*)d_in[6];
    float* out = (float*)d_out;

    const int attn_smem = (128 * 68 + 64 * 68 + 64 * 72 + 128 * 68 + 512) * 4;
    cudaFuncSetAttribute(attn_kernel,
                         cudaFuncAttributeMaxDynamicSharedMemorySize, attn_smem);

    qkv_kernel<<<dim3(64, 24), 256>>>(x, Wq, bq, Wk, bk, Wv, bv);
    attn_kernel<<<dim3(8, 128), 256, attn_smem>>>(x, out);
}

// round 6
// speedup vs baseline: 4.4133x; 1.5122x over previous
#include <cuda_runtime.h>
#include <cstdint>

#define BB 8
#define SS 1024
#define EE 1024
#define HH 16
#define DH 64

// bf16 storage (uint32 = packed bf16x2 along the contraction dim)
__device__ __align__(128) uint32_t g_Qb[(size_t)BB*HH*SS*DH/2];
__device__ __align__(128) uint32_t g_Kb[(size_t)BB*HH*SS*DH/2];
__device__ __align__(128) uint32_t g_Vb[(size_t)BB*HH*SS*DH/2];
__device__ __align__(128) uint32_t g_Wb[(size_t)3*HH*DH*EE/2];  // [zh*64+d][k/2]
__device__ __align__(128) uint32_t g_Xb[(size_t)BB*SS*EE/2];    // [m][k/2]

__device__ __forceinline__ uint32_t packbf(float lo, float hi) {
    uint32_t r;
    asm("cvt.rn.bf16x2.f32 %0, %1, %2;" : "=r"(r) : "f"(hi), "f"(lo));
    return r;
}

__device__ __forceinline__ void mma16(float* c,
    uint32_t a0, uint32_t a1, uint32_t a2, uint32_t a3, uint32_t b0, uint32_t b1)
{
    asm volatile(
        "mma.sync.aligned.m16n8k16.row.col.f32.bf16.bf16.f32 "
        "{%0,%1,%2,%3}, {%4,%5,%6,%7}, {%8,%9}, {%0,%1,%2,%3};"
        : "+f"(c[0]), "+f"(c[1]), "+f"(c[2]), "+f"(c[3])
        : "r"(a0), "r"(a1), "r"(a2), "r"(a3), "r"(b0), "r"(b1));
}

// ---------------------------------------------------------------------------
// Pre-pass A: x (f32) -> g_Xb (bf16 pairs).
// ---------------------------------------------------------------------------
__global__ __launch_bounds__(256) void convxb_kernel(const float* __restrict__ x)
{
    size_t i = ((size_t)blockIdx.x * 256 + threadIdx.x) * 4;
    float4 v = *(const float4*)(x + i);
    uint2 u = { packbf(v.x, v.y), packbf(v.z, v.w) };
    *(uint2*)(g_Xb + i / 2) = u;
}

// ---------------------------------------------------------------------------
// Pre-pass B: W [h][k][d] (f32) -> g_Wb [zh*64+d][k] (bf16 pairs, transposed).
// ---------------------------------------------------------------------------
__global__ __launch_bounds__(256) void transwb_kernel(
    const float* __restrict__ Wq, const float* __restrict__ Wk,
    const float* __restrict__ Wv)
{
    __shared__ float ts[32][65];
    const int zh = blockIdx.y;
    const int z = zh >> 4, h = zh & 15;
    const float* W = (z == 0) ? Wq : ((z == 1) ? Wk : Wv);
    W += (size_t)h * EE * DH;
    const int k0 = blockIdx.x * 32;
    const int tid = threadIdx.x;
    #pragma unroll
    for (int j = 0; j < 8; j++) {
        int idx = tid + j * 256;
        int k = idx >> 6, d = idx & 63;
        ts[k][d] = W[(size_t)(k0 + k) * DH + d];
    }
    __syncthreads();
    #pragma unroll
    for (int j = 0; j < 4; j++) {
        int idx = tid + j * 256;
        int d = idx >> 4, kp = idx & 15;
        g_Wb[((size_t)zh * DH + d) * (EE / 2) + k0 / 2 + kp] =
            packbf(ts[2 * kp][d], ts[2 * kp + 1][d]);
    }
}

// ---------------------------------------------------------------------------
// Kernel 1: fused QKV GEMM, bf16 m16n8k16.
// grid (64, 24): 64 m-tiles of 128 rows; 24 n-tiles (3z x 8 head-pairs).
// Block tile 128x128, BK=32 (16 kpairs), warps 2m x 4n (64x32 each).
// Q epilogue folds the exact 1/32 logit scale (power of two in bf16).
// ---------------------------------------------------------------------------
__global__ __launch_bounds__(256, 2) void qkvb_kernel(
    const float* __restrict__ bq, const float* __restrict__ bk,
    const float* __restrict__ bv)
{
    __shared__ uint32_t As[128 * 20];   // [m][kpair], pad 4 -> banks 4g+tg
    __shared__ uint32_t Bs[128 * 20];   // [n][kpair]

    const int tid  = threadIdx.x;
    const int lane = tid & 31;
    const int wid  = tid >> 5;
    const int g    = lane >> 2;
    const int tg   = lane & 3;
    const int wm   = (wid >> 2) * 64;
    const int wn   = (wid & 3) * 32;

    const int nt = blockIdx.y;
    const int z  = nt >> 3;
    const int h0 = (nt & 7) * 2;
    const int m0 = blockIdx.x * 128;

    const int row = tid >> 1;
    const int c0  = (tid & 1) * 8;

    const uint32_t* xp = g_Xb + (size_t)(m0 + row) * (EE / 2) + c0;
    const uint32_t* wp = g_Wb + ((size_t)(z * HH + h0) * DH + row) * (EE / 2) + c0;

    uint4 sA0 = *(const uint4*)xp,       sA1 = *(const uint4*)(xp + 4);
    uint4 sB0 = *(const uint4*)wp,       sB1 = *(const uint4*)(wp + 4);

    float c[4][4][4];
    #pragma unroll
    for (int i = 0; i < 4; i++)
        #pragma unroll
        for (int j = 0; j < 4; j++)
            #pragma unroll
            for (int k = 0; k < 4; k++) c[i][j][k] = 0.f;

    for (int kt = 0; kt < 32; kt++) {
        __syncthreads();
        {
            uint2* a2 = (uint2*)&As[row * 20 + c0];
            a2[0] = make_uint2(sA0.x, sA0.y);  a2[1] = make_uint2(sA0.z, sA0.w);
            a2[2] = make_uint2(sA1.x, sA1.y);  a2[3] = make_uint2(sA1.z, sA1.w);
            uint2* b2 = (uint2*)&Bs[row * 20 + c0];
            b2[0] = make_uint2(sB0.x, sB0.y);  b2[1] = make_uint2(sB0.z, sB0.w);
            b2[2] = make_uint2(sB1.x, sB1.y);  b2[3] = make_uint2(sB1.z, sB1.w);
        }
        __syncthreads();
        if (kt < 31) {
            int o = (kt + 1) * 16;
            sA0 = *(const uint4*)(xp + o);  sA1 = *(const uint4*)(xp + o + 4);
            sB0 = *(const uint4*)(wp + o);  sB1 = *(const uint4*)(wp + o + 4);
        }
        #pragma unroll
        for (int ks = 0; ks < 2; ks++) {
            uint32_t a[4][4], bb[4][2];
            #pragma unroll
            for (int mf = 0; mf < 4; mf++) {
                const uint32_t* p = &As[(wm + mf * 16 + g) * 20 + ks * 8 + tg];
                a[mf][0] = p[0];        a[mf][2] = p[4];
                a[mf][1] = p[8 * 20];   a[mf][3] = p[8 * 20 + 4];
            }
            #pragma unroll
            for (int nf = 0; nf < 4; nf++) {
                const uint32_t* p = &Bs[(wn + nf * 8 + g) * 20 + ks * 8 + tg];
                bb[nf][0] = p[0];  bb[nf][1] = p[4];
            }
            #pragma unroll
            for (int mf = 0; mf < 4; mf++)
                #pragma unroll
                for (int nf = 0; nf < 4; nf++)
                    mma16(c[mf][nf], a[mf][0], a[mf][1], a[mf][2], a[mf][3],
                          bb[nf][0], bb[nf][1]);
        }
    }

    // epilogue: bias, (Q: exact *1/32), pack bf16, scatter [B,H,S,Dh]
    const float* bias = (z == 0) ? bq : ((z == 1) ? bk : bv);
    uint32_t* outp    = (z == 0) ? g_Qb : ((z == 1) ? g_Kb : g_Vb);
    const float qs = (z == 0) ? 0.03125f : 1.0f;
    const int b  = blockIdx.x >> 3;
    const int s0 = m0 & 1023;

    #pragma unroll
    for (int nf = 0; nf < 4; nf++) {
        int col = wn + nf * 8 + 2 * tg;
        int h = h0 + (col >> 6), d = col & 63;
        float b0v = bias[h * DH + d], b1v = bias[h * DH + d + 1];
        uint32_t* ob = outp + (size_t)(b * HH + h) * SS * 32 + (d >> 1);
        #pragma unroll
        for (int mf = 0; mf < 4; mf++) {
            int s = s0 + wm + mf * 16 + g;
            ob[(size_t)s * 32] =
                packbf((c[mf][nf][0] + b0v) * qs, (c[mf][nf][1] + b1v) * qs);
            ob[(size_t)(s + 8) * 32] =
                packbf((c[mf][nf][2] + b0v) * qs, (c[mf][nf][3] + b1v) * qs);
        }
    }
}

// ---------------------------------------------------------------------------
// Kernel 2: flash attention, bf16 m16n8k16, fused residual epilogue.
// grid (8, 128), block 256. 128 Q-rows x 64-key tiles, warps 4m x 2n.
// ---------------------------------------------------------------------------
__global__ __launch_bounds__(256, 2) void attnb_kernel(
    const float* __restrict__ x, float* __restrict__ out)
{
    extern __shared__ uint32_t sm[];
    uint32_t* Qs = sm;                 // [128][36]  [m][dpair]  (pre-scaled)
    uint32_t* Ks = Qs + 128 * 36;      // [64][36]   [t][dpair]
    uint32_t* Vs = Ks + 64 * 36;       // [64][36]   [d][tpair]  (transposed)
    uint32_t* Ps = Vs + 64 * 36;       // [128][36]  [m][tpair]
    float* redm  = (float*)(Ps + 128 * 36);  // [128][2]
    float* reds  = redm + 256;               // [128][2]

    const int tid  = threadIdx.x;
    const int lane = tid & 31;
    const int wid  = tid >> 5;
    const int g    = lane >> 2;
    const int tg   = lane & 3;
    const int mg   = wid >> 1;
    const int nh   = wid & 1;

    const int bh = blockIdx.y;
    const int q0 = blockIdx.x * 128;
    const uint32_t* Qg = g_Qb + ((size_t)bh * SS + q0) * 32;
    const uint32_t* Kg = g_Kb + (size_t)bh * SS * 32;
    const uint32_t* Vg = g_Vb + (size_t)bh * SS * 32;

    // Q tile: straight packed copy (scale already folded at QKV epilogue)
    #pragma unroll
    for (int r = 0; r < 4; r++) {
        int idx = tid + r * 256;
        int m = idx >> 3, cc = (idx & 7) * 4;
        uint4 v = *(const uint4*)(Qg + (size_t)m * 32 + cc);
        uint2* q2 = (uint2*)&Qs[m * 36 + cc];
        q2[0] = make_uint2(v.x, v.y);  q2[1] = make_uint2(v.z, v.w);
    }

    float o[2][4][4];
    float mi[2][2], li[2][2];
    #pragma unroll
    for (int mf = 0; mf < 2; mf++) {
        mi[mf][0] = mi[mf][1] = -1e30f;
        li[mf][0] = li[mf][1] = 0.f;
        #pragma unroll
        for (int nf = 0; nf < 4; nf++)
            #pragma unroll
            for (int k = 0; k < 4; k++) o[mf][nf][k] = 0.f;
    }

    const int vt2 = tid & 31;          // tpair lane (conflict-free Vs stores)
    const int vd0 = (tid >> 5) * 8;    // d-octet per warp

    for (int t0 = 0; t0 < SS; t0 += 64) {
        __syncthreads();
        // K tile: natural [t][dpair]
        #pragma unroll
        for (int r = 0; r < 2; r++) {
            int idx = tid + r * 256;
            int t = idx >> 3, cc = (idx & 7) * 4;
            uint4 v = *(const uint4*)(Kg + (size_t)(t0 + t) * 32 + cc);
            uint2* k2 = (uint2*)&Ks[t * 36 + cc];
            k2[0] = make_uint2(v.x, v.y);  k2[1] = make_uint2(v.z, v.w);
        }
        // V tile: transpose to [d][tpair] via prmt; lane = tpair -> no conflicts
        {
            uint4 va = *(const uint4*)(Vg + (size_t)(t0 + 2 * vt2) * 32 + vd0 / 2);
            uint4 vb = *(const uint4*)(Vg + (size_t)(t0 + 2 * vt2 + 1) * 32 + vd0 / 2);
            const uint32_t aw[4] = { va.x, va.y, va.z, va.w };
            const uint32_t bw[4] = { vb.x, vb.y, vb.z, vb.w };
            #pragma unroll
            for (int j = 0; j < 4; j++) {
                Vs[(vd0 + 2 * j) * 36 + vt2]     = __byte_perm(aw[j], bw[j], 0x5410);
                Vs[(vd0 + 2 * j + 1) * 36 + vt2] = __byte_perm(aw[j], bw[j], 0x7632);
            }
        }
        __syncthreads();

        // S = Q K^T   (k = Dh = 64 -> 4 ksteps of 16)
        float s[2][4][4];
        #pragma unroll
        for (int mf = 0; mf < 2; mf++)
            #pragma unroll
            for (int nf = 0; nf < 4; nf++)
                #pragma unroll
                for (int k = 0; k < 4; k++) s[mf][nf][k] = 0.f;

        #pragma unroll
        for (int ks = 0; ks < 4; ks++) {
            uint32_t a[2][4], bb[4][2];
            #pragma unroll
            for (int mf = 0; mf < 2; mf++) {
                const uint32_t* p = &Qs[(mg * 32 + mf * 16 + g) * 36 + ks * 8 + tg];
                a[mf][0] = p[0];        a[mf][2] = p[4];
                a[mf][1] = p[8 * 36];   a[mf][3] = p[8 * 36 + 4];
            }
            #pragma unroll
            for (int nf = 0; nf < 4; nf++) {
                const uint32_t* p = &Ks[(nh * 32 + nf * 8 + g) * 36 + ks * 8 + tg];
                bb[nf][0] = p[0];  bb[nf][1] = p[4];
            }
            #pragma unroll
            for (int mf = 0; mf < 2; mf++)
                #pragma unroll
                for (int nf = 0; nf < 4; nf++)
                    mma16(s[mf][nf], a[mf][0], a[mf][1], a[mf][2], a[mf][3],
                          bb[nf][0], bb[nf][1]);
        }

        // online softmax pass 1: per-(warp,row) max partials
        #pragma unroll
        for (int mf = 0; mf < 2; mf++)
            #pragma unroll
            for (int rh = 0; rh < 2; rh++) {
                float v = -1e30f;
                #pragma unroll
                for (int nf = 0; nf < 4; nf++)
                    v = fmaxf(v, fmaxf(s[mf][nf][rh * 2], s[mf][nf][rh * 2 + 1]));
                v = fmaxf(v, __shfl_xor_sync(0xffffffffu, v, 1));
                v = fmaxf(v, __shfl_xor_sync(0xffffffffu, v, 2));
                if (tg == 0)
                    redm[(mg * 32 + mf * 16 + rh * 8 + g) * 2 + nh] = v;
            }
        __syncthreads();

        // pass 2: exp, partial sums, P -> smem (packed bf16 pairs)
        float corr[2][2];
        #pragma unroll
        for (int mf = 0; mf < 2; mf++)
            #pragma unroll
            for (int rh = 0; rh < 2; rh++) {
                int rrow = mg * 32 + mf * 16 + rh * 8 + g;
                float rmax = fmaxf(redm[rrow * 2], redm[rrow * 2 + 1]);
                float mnew = fmaxf(mi[mf][rh], rmax);
                corr[mf][rh] = __expf(mi[mf][rh] - mnew);
                mi[mf][rh] = mnew;
                float psum = 0.f;
                #pragma unroll
                for (int nf = 0; nf < 4; nf++) {
                    float p0 = __expf(s[mf][nf][rh * 2]     - mnew);
                    float p1 = __expf(s[mf][nf][rh * 2 + 1] - mnew);
                    psum += p0 + p1;
                    Ps[rrow * 36 + nh * 16 + nf * 4 + tg] = packbf(p0, p1);
                }
                psum += __shfl_xor_sync(0xffffffffu, psum, 1);
                psum += __shfl_xor_sync(0xffffffffu, psum, 2);
                if (tg == 0) reds[rrow * 2 + nh] = psum;
            }
        __syncthreads();

        #pragma unroll
        for (int mf = 0; mf < 2; mf++)
            #pragma unroll
            for (int rh = 0; rh < 2; rh++) {
                int rrow = mg * 32 + mf * 16 + rh * 8 + g;
                li[mf][rh] = li[mf][rh] * corr[mf][rh] + reds[rrow * 2] + reds[rrow * 2 + 1];
                #pragma unroll
                for (int nf = 0; nf < 4; nf++) {
                    o[mf][nf][rh * 2]     *= corr[mf][rh];
                    o[mf][nf][rh * 2 + 1] *= corr[mf][rh];
                }
            }

        // O += P V   (k = 64 keys -> 4 ksteps of 16)
        #pragma unroll
        for (int ks = 0; ks < 4; ks++) {
            uint32_t a[2][4], bb[4][2];
            #pragma unroll
            for (int mf = 0; mf < 2; mf++) {
                const uint32_t* p = &Ps[(mg * 32 + mf * 16 + g) * 36 + ks * 8 + tg];
                a[mf][0] = p[0];        a[mf][2] = p[4];
                a[mf][1] = p[8 * 36];   a[mf][3] = p[8 * 36 + 4];
            }
            #pragma unroll
            for (int nf = 0; nf < 4; nf++) {
                const uint32_t* p = &Vs[(nh * 32 + nf * 8 + g) * 36 + ks * 8 + tg];
                bb[nf][0] = p[0];  bb[nf][1] = p[4];
            }
            #pragma unroll
            for (int mf = 0; mf < 2; mf++)
                #pragma unroll
                for (int nf = 0; nf < 4; nf++)
                    mma16(o[mf][nf], a[mf][0], a[mf][1], a[mf][2], a[mf][3],
                          bb[nf][0], bb[nf][1]);
        }
    }

    // epilogue: out = x + O/li, scatter head slice into [B,S,E] (f32)
    const int b = bh >> 4, h = bh & 15;
    #pragma unroll
    for (int mf = 0; mf < 2; mf++)
        #pragma unroll
        for (int rh = 0; rh < 2; rh++) {
            float inv = 1.f / li[mf][rh];
            int r = mg * 32 + mf * 16 + rh * 8 + g;
            size_t base = ((size_t)(b * SS + q0 + r)) * EE + h * DH;
            #pragma unroll
            for (int nf = 0; nf < 4; nf++) {
                int d = nh * 32 + nf * 8 + 2 * tg;
                float2 xv = *(const float2*)(x + base + d);
                float2 ov = { xv.x + o[mf][nf][rh * 2] * inv,
                              xv.y + o[mf][nf][rh * 2 + 1] * inv };
                *(float2*)(out + base + d) = ov;
            }
        }
}

// ---------------------------------------------------------------------------
extern "C" void kernel_launch(void* const* d_in, const int* in_sizes, int n_in,
                              void* d_out, int out_size)
{
    const float* x  = (const float*)d_in[0];
    const float* Wq = (const float*)d_in[1];
    const float* bq = (const float*)d_in[2];
    const float* Wk = (const float*)d_in[3];
    const float* bk = (const float*)d_in[4];
    const float* Wv = (const float*)d_in[5];
    const float* bv = (const float*)d_in[6];
    float* out = (float*)d_out;

    const int attn_smem = (128 * 36 + 64 * 36 + 64 * 36 + 128 * 36 + 512) * 4; // 57344
    cudaFuncSetAttribute(attnb_kernel,
                         cudaFuncAttributeMaxDynamicSharedMemorySize, attn_smem);

    convxb_kernel<<<(BB * SS * EE) / (256 * 4), 256>>>(x);
    transwb_kernel<<<dim3(32, 48), 256>>>(Wq, Wk, Wv);
    qkvb_kernel<<<dim3(64, 24), 256>>>(bq, bk, bv);
    attnb_kernel<<<dim3(8, 128), 256, attn_smem>>>(x, out);
}